// round 1
// baseline (speedup 1.0000x reference)
#include <cuda_runtime.h>

// Problem dims
#define S    1024      // tokens per (b,n) sequence = V*W
#define CD   64        // input channels
#define DD   256       // SPA
#define FD   512       // 2*SPA
#define BNT  32        // B*N sequences

// Scratch (device globals — allocation-free rule)
__device__ __align__(256) float g_t  [BNT * S * DD];   // 32 MB  (pre-norm t, also residual)
__device__ __align__(256) float g_tn [BNT * S * DD];   // 32 MB  (tn, reused as hn after attention)
__device__ __align__(256) float g_p  [(long)BNT * S * S]; // 128 MB (scores -> normalized p)
__device__ __align__(256) float g_att[BNT * S * DD];   // 32 MB  (att, reused as y)
__device__ __align__(256) float g_hf [BNT * S * FD];   // 64 MB  (FFN hidden)

// ---------------------------------------------------------------------------
// Generic fp32 GEMM: C[m][n] = sum_k A(m,k) * B(n,k or k,n)  [+ epilogue]
//   A_KM : A stored [K,M] (column-major in m) vs [M,K] row-major
//   B_KN : B stored [K,N] vs [N,K]
//   EPI  : 0=store, 1=relu-store, 2=store + residual R, 3=scatter to output
//   CAUSAL: 0=none, 1=skip tiles with ntile>mtile (scores), 2=limit K to qtile end (P@V)
// Tiles: 64x64x16, 256 threads, 4x4 per thread.
// ---------------------------------------------------------------------------
template<int A_KM, int B_KN, int EPI, int CAUSAL>
__global__ __launch_bounds__(256)
void gemm_k(const float* __restrict__ A, long sbA, long snA, int lda,
            const float* __restrict__ B, long sbB, long snB, int ldb,
            float* __restrict__ Cp, long sbC, long snC, int ldc,
            const float* __restrict__ R, long sbR, long snR,
            float* __restrict__ Op,
            int K)
{
    const int bx = blockIdx.x, by = blockIdx.y, bz = blockIdx.z;
    if (CAUSAL == 1 && bx > by) return;        // strictly-upper causal tile: skip

    const int b = bz >> 3, n = bz & 7;
    const float* Ab = A + (long)b * sbA + (long)n * snA;
    const float* Bb = B + (long)b * sbB + (long)n * snB;

    const int m0 = by * 64, n0 = bx * 64;

    __shared__ float sA[16][68];
    __shared__ float sB[16][68];

    const int tid = threadIdx.x;
    const int tx = tid & 15, ty = tid >> 4;

    float acc[4][4] = {};

    int Keff = K;
    if (CAUSAL == 2) { int lim = (by + 1) * 64; if (lim < Keff) Keff = lim; }

    for (int k0 = 0; k0 < Keff; k0 += 16) {
        // ---- load A tile into sA[k][m] ----
        if (A_KM) {
            int k  = tid >> 4;            // 0..15
            int m4 = (tid & 15) * 4;      // 0..60
            float4 v = *(const float4*)(Ab + (long)(k0 + k) * lda + m0 + m4);
            *(float4*)&sA[k][m4] = v;
        } else {
            int mm = tid >> 2;            // 0..63
            int k4 = (tid & 3) * 4;       // 0..12
            float4 v = *(const float4*)(Ab + (long)(m0 + mm) * lda + k0 + k4);
            sA[k4 + 0][mm] = v.x; sA[k4 + 1][mm] = v.y;
            sA[k4 + 2][mm] = v.z; sA[k4 + 3][mm] = v.w;
        }
        // ---- load B tile into sB[k][n] ----
        if (B_KN) {
            int k  = tid >> 4;
            int n4 = (tid & 15) * 4;
            float4 v = *(const float4*)(Bb + (long)(k0 + k) * ldb + n0 + n4);
            *(float4*)&sB[k][n4] = v;
        } else {
            int nn = tid >> 2;
            int k4 = (tid & 3) * 4;
            float4 v = *(const float4*)(Bb + (long)(n0 + nn) * ldb + k0 + k4);
            sB[k4 + 0][nn] = v.x; sB[k4 + 1][nn] = v.y;
            sB[k4 + 2][nn] = v.z; sB[k4 + 3][nn] = v.w;
        }
        __syncthreads();

        #pragma unroll
        for (int k = 0; k < 16; k++) {
            float4 av = *(const float4*)&sA[k][ty * 4];
            float4 bv = *(const float4*)&sB[k][tx * 4];
            float am[4] = {av.x, av.y, av.z, av.w};
            float bm[4] = {bv.x, bv.y, bv.z, bv.w};
            #pragma unroll
            for (int i = 0; i < 4; i++)
                #pragma unroll
                for (int j = 0; j < 4; j++)
                    acc[i][j] += am[i] * bm[j];
        }
        __syncthreads();
    }

    // ---- epilogue ----
    if (EPI == 3) {
        // out[((b*64 + c)*8 + n)*1024 + m], c = GEMM n-index, m = token
        #pragma unroll
        for (int i = 0; i < 4; i++) {
            int m = m0 + ty * 4 + i;
            #pragma unroll
            for (int j = 0; j < 4; j++) {
                int c = n0 + tx * 4 + j;
                Op[(((long)b * 64 + c) * 8 + n) * 1024 + m] = acc[i][j];
            }
        }
    } else {
        float* Cb = Cp + (long)b * sbC + (long)n * snC;
        const float* Rb = (EPI == 2) ? (R + (long)b * sbR + (long)n * snR) : nullptr;
        #pragma unroll
        for (int i = 0; i < 4; i++) {
            int m = m0 + ty * 4 + i;
            float4 v = make_float4(acc[i][0], acc[i][1], acc[i][2], acc[i][3]);
            if (EPI == 1) {
                v.x = fmaxf(v.x, 0.f); v.y = fmaxf(v.y, 0.f);
                v.z = fmaxf(v.z, 0.f); v.w = fmaxf(v.w, 0.f);
            }
            if (EPI == 2) {
                float4 r = *(const float4*)(Rb + (long)m * ldc + n0 + tx * 4);
                v.x += r.x; v.y += r.y; v.z += r.z; v.w += r.w;
            }
            *(float4*)(Cb + (long)m * ldc + n0 + tx * 4) = v;
        }
    }
}

// ---------------------------------------------------------------------------
// LayerNorm over rows of 256, one warp per token row.
// ---------------------------------------------------------------------------
__global__ __launch_bounds__(256)
void ln_k(const float* __restrict__ in, float* __restrict__ out,
          const float* __restrict__ gam, const float* __restrict__ bet)
{
    int warp = (blockIdx.x * blockDim.x + threadIdx.x) >> 5;   // 0..BNT*S-1
    int lane = threadIdx.x & 31;
    const float* x = in + (long)warp * DD;

    float v[8];
    float s = 0.f, ss = 0.f;
    #pragma unroll
    for (int i = 0; i < 8; i++) {
        v[i] = x[lane + 32 * i];
        s  += v[i];
        ss += v[i] * v[i];
    }
    #pragma unroll
    for (int o = 16; o; o >>= 1) {
        s  += __shfl_xor_sync(0xffffffffu, s,  o);
        ss += __shfl_xor_sync(0xffffffffu, ss, o);
    }
    float mu  = s * (1.f / DD);
    float var = ss * (1.f / DD) - mu * mu;
    float rs  = rsqrtf(var + 1e-5f);

    float* o_ = out + (long)warp * DD;
    #pragma unroll
    for (int i = 0; i < 8; i++) {
        int c = lane + 32 * i;
        o_[c] = (v[i] - mu) * rs * gam[c] + bet[c];
    }
}

// ---------------------------------------------------------------------------
// Causal masked softmax, one warp per query row; writes normalized p.
// Only columns [0, roundup(q+1,64)) are written; upper tiles never touched.
// ---------------------------------------------------------------------------
__global__ __launch_bounds__(256)
void softmax_k(float* __restrict__ p)
{
    int warp = (blockIdx.x * blockDim.x + threadIdx.x) >> 5;   // row 0..BNT*S-1
    int lane = threadIdx.x & 31;
    int q = warp & (S - 1);
    float* row = p + (long)warp * S;

    float v[32];
    float mx = -3.4e38f;
    #pragma unroll
    for (int i = 0; i < 32; i++) {
        int col = lane + 32 * i;
        v[i] = (col <= q) ? row[col] : -3.4e38f;
        mx = fmaxf(mx, v[i]);
    }
    #pragma unroll
    for (int o = 16; o; o >>= 1) mx = fmaxf(mx, __shfl_xor_sync(0xffffffffu, mx, o));

    float sum = 0.f;
    #pragma unroll
    for (int i = 0; i < 32; i++) {
        int col = lane + 32 * i;
        v[i] = (col <= q) ? expf(v[i] - mx) : 0.f;
        sum += v[i];
    }
    #pragma unroll
    for (int o = 16; o; o >>= 1) sum += __shfl_xor_sync(0xffffffffu, sum, o);
    float inv = 1.f / sum;

    int kend = ((q >> 6) + 1) << 6;   // end of diagonal tile
    #pragma unroll
    for (int i = 0; i < 32; i++) {
        int col = lane + 32 * i;
        if (col < kend) row[col] = v[i] * inv;
    }
}

// ---------------------------------------------------------------------------
extern "C" void kernel_launch(void* const* d_in, const int* in_sizes, int n_in,
                              void* d_out, int out_size)
{
    (void)in_sizes; (void)n_in; (void)out_size;
    const float* buffer = (const float*)d_in[0];   // [4,64,8,32,32]
    const float* W_in   = (const float*)d_in[1];   // [256,64]
    const float* ln1_g  = (const float*)d_in[2];
    const float* ln1_b  = (const float*)d_in[3];
    const float* ln2_g  = (const float*)d_in[4];
    const float* ln2_b  = (const float*)d_in[5];
    const float* W1     = (const float*)d_in[6];   // [512,256]
    const float* W2     = (const float*)d_in[7];   // [256,512]
    const float* W_out  = (const float*)d_in[8];   // [64,256]
    float* out = (float*)d_out;

    float *t, *tn, *p, *att, *hf;
    cudaGetSymbolAddress((void**)&t,   g_t);
    cudaGetSymbolAddress((void**)&tn,  g_tn);
    cudaGetSymbolAddress((void**)&p,   g_p);
    cudaGetSymbolAddress((void**)&att, g_att);
    cudaGetSymbolAddress((void**)&hf,  g_hf);

    const long sbT = 8L * S * DD, snT = (long)S * DD;    // t/tn/att strides
    const long sbP = 8L * S * S,  snP = (long)S * S;     // p strides
    const long sbH = 8L * S * FD, snH = (long)S * FD;    // hf strides
    // buffer per-(b,n) base: b*524288 + n*1024 ; element (c,s): c*8192 + s
    const long sbX = 64L * 8 * 1024, snX = 1024;

    // 1) t = x . W_in^T     (A as [K=64, M] from buffer; B = [256,64])
    gemm_k<1, 0, 0, 0><<<dim3(4, 16, BNT), 256>>>(
        buffer, sbX, snX, 8192,
        W_in,   0, 0, CD,
        t,      sbT, snT, DD,
        nullptr, 0, 0, nullptr, CD);

    // 2) tn = LN1(t)
    ln_k<<<(BNT * S) / 8, 256>>>(t, tn, ln1_g, ln1_b);

    // 3) scores = tn . tn^T  (causal tile skip)
    gemm_k<0, 0, 0, 1><<<dim3(16, 16, BNT), 256>>>(
        tn, sbT, snT, DD,
        tn, sbT, snT, DD,
        p,  sbP, snP, S,
        nullptr, 0, 0, nullptr, DD);

    // 4) masked softmax -> normalized p
    softmax_k<<<(BNT * S) / 8, 256>>>(p);

    // 5) att = p . t + t    (k-tile limit = qtile)
    gemm_k<0, 1, 2, 2><<<dim3(4, 16, BNT), 256>>>(
        p,  sbP, snP, S,
        t,  sbT, snT, DD,
        att, sbT, snT, DD,
        t,  sbT, snT, nullptr, S);

    // 6) hn = LN2(att)  (reuse tn buffer)
    ln_k<<<(BNT * S) / 8, 256>>>(att, tn, ln2_g, ln2_b);

    // 7) hf = relu(hn . W1^T)
    gemm_k<0, 0, 1, 0><<<dim3(8, 16, BNT), 256>>>(
        tn, sbT, snT, DD,
        W1, 0, 0, DD,
        hf, sbH, snH, FD,
        nullptr, 0, 0, nullptr, DD);

    // 8) y = hf . W2^T + t  (reuse att buffer as y)
    gemm_k<0, 0, 2, 0><<<dim3(4, 16, BNT), 256>>>(
        hf, sbH, snH, FD,
        W2, 0, 0, FD,
        att, sbT, snT, DD,
        t,  sbT, snT, nullptr, FD);

    // 9) out = y . W_out^T, scattered into (b,c,n,s) layout
    gemm_k<0, 0, 3, 0><<<dim3(1, 16, BNT), 256>>>(
        att, sbT, snT, DD,
        W_out, 0, 0, DD,
        nullptr, 0, 0, 0,
        nullptr, 0, 0, out, DD);
}

// round 3
// speedup vs baseline: 1.7497x; 1.7497x over previous
#include <cuda_runtime.h>
#include <cstdint>

#define S    1024
#define CD   64
#define DD   256
#define FD   512
#define BNT  32

// Scratch
__device__ __align__(256) float g_xt [BNT * S * CD];      // 8 MB  x transposed [bn][s][c]
__device__ __align__(256) float g_t  [BNT * S * DD];      // 32 MB
__device__ __align__(256) float g_tT [BNT * S * DD];      // 32 MB t transposed [bn][d][s]
__device__ __align__(256) float g_tn [BNT * S * DD];      // 32 MB
__device__ __align__(256) float g_p  [(long)BNT * S * S]; // 128 MB
__device__ __align__(256) float g_att[BNT * S * DD];      // 32 MB
__device__ __align__(256) float g_hf [BNT * S * FD];      // 64 MB

// ---------------------------------------------------------------------------
// tf32 helpers
// ---------------------------------------------------------------------------
__device__ __forceinline__ float tf32r(float x) {
    uint32_t u;
    asm("cvt.rna.tf32.f32 %0, %1;" : "=r"(u) : "f"(x));
    return __uint_as_float(u);
}

#define MMA_TF32(d, a0, a1, a2, a3, b0, b1)                                   \
    asm volatile("mma.sync.aligned.m16n8k8.row.col.f32.tf32.tf32.f32 "        \
                 "{%0,%1,%2,%3}, {%4,%5,%6,%7}, {%8,%9}, {%0,%1,%2,%3};\n"    \
                 : "+f"(d[0]), "+f"(d[1]), "+f"(d[2]), "+f"(d[3])             \
                 : "r"(a0), "r"(a1), "r"(a2), "r"(a3), "r"(b0), "r"(b1))

#define UF(x) __float_as_uint(x)

// swizzled word address inside a [rows][16] tile block
__device__ __forceinline__ int sw_addr(int m, int q) {
    return m * 16 + (((q ^ ((m >> 1) & 3)) & 3) << 2);
}

// ---------------------------------------------------------------------------
// tf32 mma GEMM: C[m][n] = sum_k A[m][k]*B[n][k]  (A,B row-major [M][K]/[N][K])
// CTA tile 128x64x16, 8 warps (4x2), warp tile 32x32.
// SPLIT : 3xTF32 (hi*hi + hi*lo + lo*hi) for fp32-grade accuracy
// EPI   : 0 store, 1 relu, 2 +residual R, 3 scatter to output layout
// CAUSAL: 1 tile skip (scores), 2 K limited to m0+128 (P@V)
// ---------------------------------------------------------------------------
template<int SPLIT, int EPI, int CAUSAL>
__global__ __launch_bounds__(256, SPLIT ? 1 : 2)
void mma_gemm(const float* __restrict__ A, long sAbn, int lda,
              const float* __restrict__ B, long sBbn, int ldb,
              float* __restrict__ C, long sCbn, int ldc,
              const float* __restrict__ R, long sRbn,
              float* __restrict__ Op, int K)
{
    const int bx = blockIdx.x, by = blockIdx.y, bz = blockIdx.z;
    if (CAUSAL == 1 && bx > 2 * by + 1) return;

    __shared__ __align__(16) float sh[SPLIT ? 6144 : 3072];
    float* sAhi = sh;                     // [128][16] swizzled
    float* sBhi = sh + 2048;              // [64][16]
    float* sAlo = SPLIT ? sh + 3072 : sh;
    float* sBlo = SPLIT ? sh + 5120 : sh;

    const int tid = threadIdx.x;
    const int w = tid >> 5, l = tid & 31;
    const int warp_m = (w & 3) * 32, warp_n = (w >> 2) * 32;
    const int g = l >> 2, cc = l & 3;

    const int m0 = by * 128, n0 = bx * 64;
    const float* Ab = A + (long)bz * sAbn;
    const float* Bb = B + (long)bz * sBbn;

    int Keff = K;
    if (CAUSAL == 2) { int lim = m0 + 128; if (lim < Keff) Keff = lim; }
    const int nk = Keff >> 4;

    // loader indices: A rows m0+am, m0+am+64 ; B row n0+am ; 4 floats at k0+aj*4
    const int am = tid >> 2, aj = tid & 3;
    const float* aptr0 = Ab + (long)(m0 + am) * lda + aj * 4;
    const float* aptr1 = Ab + (long)(m0 + am + 64) * lda + aj * 4;
    const float* bptr  = Bb + (long)(n0 + am) * ldb + aj * 4;

    float acc[2][4][4];
    #pragma unroll
    for (int i = 0; i < 2; i++)
        #pragma unroll
        for (int j = 0; j < 4; j++)
            #pragma unroll
            for (int r = 0; r < 4; r++) acc[i][j][r] = 0.f;

    float4 ra0 = *(const float4*)aptr0;
    float4 ra1 = *(const float4*)aptr1;
    float4 rb  = *(const float4*)bptr;

    for (int kt = 0; kt < nk; kt++) {
        // ---- convert + swizzled store ----
        {
            float va[4] = {ra0.x, ra0.y, ra0.z, ra0.w};
            float vb[4] = {ra1.x, ra1.y, ra1.z, ra1.w};
            float vc[4] = {rb.x,  rb.y,  rb.z,  rb.w};
            #pragma unroll
            for (int r = 0; r < 4; r++) {
                int wa = sw_addr(am, r) + aj;
                int wb = sw_addr(am + 64, r) + aj;
                int wc = sw_addr(am, r) + aj;
                float ha = tf32r(va[r]), hb = tf32r(vb[r]), hc = tf32r(vc[r]);
                sAhi[wa] = ha; sAhi[wb] = hb; sBhi[wc] = hc;
                if (SPLIT) {
                    sAlo[wa] = tf32r(va[r] - ha);
                    sAlo[wb] = tf32r(vb[r] - hb);
                    sBlo[wc] = tf32r(vc[r] - hc);
                }
            }
        }
        __syncthreads();

        if (kt + 1 < nk) {
            ra0 = *(const float4*)(aptr0 + (kt + 1) * 16);
            ra1 = *(const float4*)(aptr1 + (kt + 1) * 16);
            rb  = *(const float4*)(bptr  + (kt + 1) * 16);
        }

        // ---- fragments ----
        float4 Ah[2][2], Bh[4], Al[2][2], Bl[4];
        #pragma unroll
        for (int mi = 0; mi < 2; mi++) {
            int mr = warp_m + mi * 16 + g;
            Ah[mi][0] = *(const float4*)&sAhi[sw_addr(mr, cc)];
            Ah[mi][1] = *(const float4*)&sAhi[sw_addr(mr + 8, cc)];
            if (SPLIT) {
                Al[mi][0] = *(const float4*)&sAlo[sw_addr(mr, cc)];
                Al[mi][1] = *(const float4*)&sAlo[sw_addr(mr + 8, cc)];
            }
        }
        #pragma unroll
        for (int nj = 0; nj < 4; nj++) {
            int nr = warp_n + nj * 8 + g;
            Bh[nj] = *(const float4*)&sBhi[sw_addr(nr, cc)];
            if (SPLIT) Bl[nj] = *(const float4*)&sBlo[sw_addr(nr, cc)];
        }

        // ---- mma: two k8 steps per BK16 ----
        #pragma unroll
        for (int mi = 0; mi < 2; mi++) {
            #pragma unroll
            for (int nj = 0; nj < 4; nj++) {
                float* d = acc[mi][nj];
                // step 0 (x,y comps)
                MMA_TF32(d, UF(Ah[mi][0].x), UF(Ah[mi][1].x), UF(Ah[mi][0].y), UF(Ah[mi][1].y),
                            UF(Bh[nj].x), UF(Bh[nj].y));
                if (SPLIT) {
                    MMA_TF32(d, UF(Ah[mi][0].x), UF(Ah[mi][1].x), UF(Ah[mi][0].y), UF(Ah[mi][1].y),
                                UF(Bl[nj].x), UF(Bl[nj].y));
                    MMA_TF32(d, UF(Al[mi][0].x), UF(Al[mi][1].x), UF(Al[mi][0].y), UF(Al[mi][1].y),
                                UF(Bh[nj].x), UF(Bh[nj].y));
                }
                // step 1 (z,w comps)
                MMA_TF32(d, UF(Ah[mi][0].z), UF(Ah[mi][1].z), UF(Ah[mi][0].w), UF(Ah[mi][1].w),
                            UF(Bh[nj].z), UF(Bh[nj].w));
                if (SPLIT) {
                    MMA_TF32(d, UF(Ah[mi][0].z), UF(Ah[mi][1].z), UF(Ah[mi][0].w), UF(Ah[mi][1].w),
                                UF(Bl[nj].z), UF(Bl[nj].w));
                    MMA_TF32(d, UF(Al[mi][0].z), UF(Al[mi][1].z), UF(Al[mi][0].w), UF(Al[mi][1].w),
                                UF(Bh[nj].z), UF(Bh[nj].w));
                }
            }
        }
        __syncthreads();
    }

    // ---- epilogue ----
    if (EPI == 3) {
        const int b = bz >> 3, n = bz & 7;
        #pragma unroll
        for (int mi = 0; mi < 2; mi++) {
            #pragma unroll
            for (int nj = 0; nj < 4; nj++) {
                int row = m0 + warp_m + mi * 16 + g;
                int col = n0 + warp_n + nj * 8 + 2 * cc;
                Op[((long)(b * 64 + col)     * 8 + n) * 1024 + row]     = acc[mi][nj][0];
                Op[((long)(b * 64 + col + 1) * 8 + n) * 1024 + row]     = acc[mi][nj][1];
                Op[((long)(b * 64 + col)     * 8 + n) * 1024 + row + 8] = acc[mi][nj][2];
                Op[((long)(b * 64 + col + 1) * 8 + n) * 1024 + row + 8] = acc[mi][nj][3];
            }
        }
    } else {
        float* Cb = C + (long)bz * sCbn;
        const float* Rb = (EPI == 2) ? (R + (long)bz * sRbn) : nullptr;
        #pragma unroll
        for (int mi = 0; mi < 2; mi++) {
            #pragma unroll
            for (int nj = 0; nj < 4; nj++) {
                int row = m0 + warp_m + mi * 16 + g;
                int col = n0 + warp_n + nj * 8 + 2 * cc;
                float2 v01 = make_float2(acc[mi][nj][0], acc[mi][nj][1]);
                float2 v23 = make_float2(acc[mi][nj][2], acc[mi][nj][3]);
                if (EPI == 1) {
                    v01.x = fmaxf(v01.x, 0.f); v01.y = fmaxf(v01.y, 0.f);
                    v23.x = fmaxf(v23.x, 0.f); v23.y = fmaxf(v23.y, 0.f);
                }
                if (EPI == 2) {
                    float2 r0 = *(const float2*)(Rb + (long)row * ldc + col);
                    float2 r1 = *(const float2*)(Rb + (long)(row + 8) * ldc + col);
                    v01.x += r0.x; v01.y += r0.y;
                    v23.x += r1.x; v23.y += r1.y;
                }
                *(float2*)(Cb + (long)row * ldc + col) = v01;
                *(float2*)(Cb + (long)(row + 8) * ldc + col) = v23;
            }
        }
    }
}

// ---------------------------------------------------------------------------
// transposes
// ---------------------------------------------------------------------------
__global__ __launch_bounds__(256)
void transpose_x_k(const float* __restrict__ x, float* __restrict__ xt)
{
    __shared__ float tile[32][33];
    int tx = threadIdx.x & 31, ty = threadIdx.x >> 5;      // block (32,8) flat
    int bn = blockIdx.z, b = bn >> 3, n = bn & 7;
    int s0 = blockIdx.x * 32, c0 = blockIdx.y * 32;
    const float* src = x + ((long)b * 64 * 8 + n) * 1024;  // (ch,s): +ch*8192+s
    #pragma unroll
    for (int i = 0; i < 4; i++)
        tile[ty + 8 * i][tx] = src[(long)(c0 + ty + 8 * i) * 8192 + s0 + tx];
    __syncthreads();
    float* dst = xt + (long)bn * (S * CD);
    #pragma unroll
    for (int i = 0; i < 4; i++)
        dst[(long)(s0 + ty + 8 * i) * 64 + c0 + tx] = tile[tx][ty + 8 * i];
}

__global__ __launch_bounds__(256)
void transpose_t_k(const float* __restrict__ t, float* __restrict__ tT)
{
    __shared__ float tile[32][33];
    int tx = threadIdx.x & 31, ty = threadIdx.x >> 5;
    int bn = blockIdx.z;
    int s0 = blockIdx.x * 32, d0 = blockIdx.y * 32;
    const float* src = t + (long)bn * (S * DD);
    #pragma unroll
    for (int i = 0; i < 4; i++)
        tile[ty + 8 * i][tx] = src[(long)(s0 + ty + 8 * i) * 256 + d0 + tx];
    __syncthreads();
    float* dst = tT + (long)bn * (S * DD);
    #pragma unroll
    for (int i = 0; i < 4; i++)
        dst[(long)(d0 + ty + 8 * i) * 1024 + s0 + tx] = tile[tx][ty + 8 * i];
}

// ---------------------------------------------------------------------------
// LayerNorm (one warp per 256-wide row)
// ---------------------------------------------------------------------------
__global__ __launch_bounds__(256)
void ln_k(const float* __restrict__ in, float* __restrict__ out,
          const float* __restrict__ gam, const float* __restrict__ bet)
{
    int warp = (blockIdx.x * blockDim.x + threadIdx.x) >> 5;
    int lane = threadIdx.x & 31;
    const float* x = in + (long)warp * DD;

    float v[8], s = 0.f, ss = 0.f;
    #pragma unroll
    for (int i = 0; i < 8; i++) {
        v[i] = x[lane + 32 * i];
        s += v[i]; ss += v[i] * v[i];
    }
    #pragma unroll
    for (int o = 16; o; o >>= 1) {
        s  += __shfl_xor_sync(0xffffffffu, s,  o);
        ss += __shfl_xor_sync(0xffffffffu, ss, o);
    }
    float mu = s * (1.f / DD);
    float var = ss * (1.f / DD) - mu * mu;
    float rs = rsqrtf(var + 1e-5f);

    float* o_ = out + (long)warp * DD;
    #pragma unroll
    for (int i = 0; i < 8; i++) {
        int c = lane + 32 * i;
        o_[c] = (v[i] - mu) * rs * gam[c] + bet[c];
    }
}

// ---------------------------------------------------------------------------
// Causal softmax (one warp per query row); zero-fill up to 128-tile boundary
// ---------------------------------------------------------------------------
__global__ __launch_bounds__(256)
void softmax_k(float* __restrict__ p)
{
    int warp = (blockIdx.x * blockDim.x + threadIdx.x) >> 5;
    int lane = threadIdx.x & 31;
    int q = warp & (S - 1);
    float* row = p + (long)warp * S;

    float v[32], mx = -3.4e38f;
    #pragma unroll
    for (int i = 0; i < 32; i++) {
        int col = lane + 32 * i;
        v[i] = (col <= q) ? row[col] : -3.4e38f;
        mx = fmaxf(mx, v[i]);
    }
    #pragma unroll
    for (int o = 16; o; o >>= 1) mx = fmaxf(mx, __shfl_xor_sync(0xffffffffu, mx, o));

    float sum = 0.f;
    #pragma unroll
    for (int i = 0; i < 32; i++) {
        int col = lane + 32 * i;
        v[i] = (col <= q) ? expf(v[i] - mx) : 0.f;
        sum += v[i];
    }
    #pragma unroll
    for (int o = 16; o; o >>= 1) sum += __shfl_xor_sync(0xffffffffu, sum, o);
    float inv = 1.f / sum;

    int kend = ((q >> 7) + 1) << 7;          // 128-tile boundary (P@V K-limit)
    #pragma unroll
    for (int i = 0; i < 32; i++) {
        int col = lane + 32 * i;
        if (col < kend) row[col] = v[i] * inv;
    }
}

// ---------------------------------------------------------------------------
extern "C" void kernel_launch(void* const* d_in, const int* in_sizes, int n_in,
                              void* d_out, int out_size)
{
    (void)in_sizes; (void)n_in; (void)out_size;
    const float* buffer = (const float*)d_in[0];
    const float* W_in   = (const float*)d_in[1];
    const float* ln1_g  = (const float*)d_in[2];
    const float* ln1_b  = (const float*)d_in[3];
    const float* ln2_g  = (const float*)d_in[4];
    const float* ln2_b  = (const float*)d_in[5];
    const float* W1     = (const float*)d_in[6];
    const float* W2     = (const float*)d_in[7];
    const float* W_out  = (const float*)d_in[8];
    float* out = (float*)d_out;

    float *xt, *t, *tT, *tn, *p, *att, *hf;
    cudaGetSymbolAddress((void**)&xt,  g_xt);
    cudaGetSymbolAddress((void**)&t,   g_t);
    cudaGetSymbolAddress((void**)&tT,  g_tT);
    cudaGetSymbolAddress((void**)&tn,  g_tn);
    cudaGetSymbolAddress((void**)&p,   g_p);
    cudaGetSymbolAddress((void**)&att, g_att);
    cudaGetSymbolAddress((void**)&hf,  g_hf);

    const long sT = (long)S * DD;     // 262144
    const long sP = (long)S * S;      // 1048576
    const long sH = (long)S * FD;     // 524288
    const long sX = (long)S * CD;     // 65536

    // 0) transpose x -> xt [bn][s][c]
    transpose_x_k<<<dim3(32, 2, BNT), 256>>>(buffer, xt);

    // 1) t = xt . W_in^T   (SPLIT: feeds the sensitive score path)
    mma_gemm<1, 0, 0><<<dim3(4, 8, BNT), 256>>>(
        xt, sX, CD,  W_in, 0, CD,  t, sT, DD,  nullptr, 0, nullptr, CD);

    // 2) tn = LN1(t)
    ln_k<<<(BNT * S) / 8, 256>>>(t, tn, ln1_g, ln1_b);

    // 3) scores = tn . tn^T  (SPLIT, causal tile skip)
    mma_gemm<1, 0, 1><<<dim3(16, 8, BNT), 256>>>(
        tn, sT, DD,  tn, sT, DD,  p, sP, S,  nullptr, 0, nullptr, DD);

    // 4) softmax
    softmax_k<<<(BNT * S) / 8, 256>>>(p);

    // 5) transpose t -> tT [bn][d][s]
    transpose_t_k<<<dim3(32, 8, BNT), 256>>>(t, tT);

    // 6) att = p . t + t    (single tf32, K limited to m0+128)
    mma_gemm<0, 2, 2><<<dim3(4, 8, BNT), 256>>>(
        p, sP, S,  tT, sT, S,  att, sT, DD,  t, sT, nullptr, S);

    // 7) hn = LN2(att)  -> tn
    ln_k<<<(BNT * S) / 8, 256>>>(att, tn, ln2_g, ln2_b);

    // 8) hf = relu(hn . W1^T)
    mma_gemm<0, 1, 0><<<dim3(8, 8, BNT), 256>>>(
        tn, sT, DD,  W1, 0, DD,  hf, sH, FD,  nullptr, 0, nullptr, DD);

    // 9) y = hf . W2^T + t  -> att
    mma_gemm<0, 2, 0><<<dim3(4, 8, BNT), 256>>>(
        hf, sH, FD,  W2, 0, FD,  att, sT, DD,  t, sT, nullptr, FD);

    // 10) out = y . W_out^T (SPLIT, scatter epilogue)
    mma_gemm<1, 3, 0><<<dim3(1, 8, BNT), 256>>>(
        att, sT, DD,  W_out, 0, DD,  nullptr, 0, 0,  nullptr, 0, out, DD);
}